// round 6
// baseline (speedup 1.0000x reference)
#include <cuda_runtime.h>
#include <math.h>

// Problem constants
#define Bc 8
#define Cc 64
#define Hc 192
#define Wc 256
#define WS 16            // columns per CTA slab
#define NSLAB 16         // Wc / WS
#define RW 18            // ring row width (WS + 2 halo)
#define RSLOT (Cc*RW)    // float2 elements per ring slot (1152)
#define NPF 5            // prefetch regs per thread: ceil(1152/256)

// shared memory byte offsets
#define OFF_W     0
#define SZ_W      (576*64*4)             // 147456: weights [tap=ci*9+kh*3+kw][co]
#define OFF_RING  (OFF_W + SZ_W)         // 147456
#define SZ_RING   (5*RSLOT*8)            // 46080: 3 updated slots + 2 orig slots, dup float2
#define OFF_ORIG  (OFF_RING + SZ_RING)   // 193536
#define SZ_ORIG   (2*64*16*4)            // 8192: orig row scalar, double buffered
#define OFF_RED   (OFF_ORIG + SZ_ORIG)   // 201728
#define SZ_RED    (4*16*68*4)            // 17408: partials [ci_g*16+w][co] pad 68 (2-way optimal)
#define OFF_BIAS  (OFF_RED + SZ_RED)     // 219136
#define SZ_BIAS   256
#define SMEM_TOTAL (OFF_BIAS + SZ_BIAS)  // 219392

__device__ int g_flags[Bc*NSLAB];

// acquire-load with compiler memory barrier: the "memory" clobber prevents the
// compiler from hoisting the subsequent halo LDG above the spin loop (only a
// control dependence ties them otherwise).
__device__ __forceinline__ int ld_acq(const int* p) {
    int v;
    asm volatile("ld.global.acquire.gpu.b32 %0, [%1];" : "=r"(v) : "l"(p) : "memory");
    return v;
}
__device__ __forceinline__ void st_rel(int* p, int v) {
    asm volatile("st.global.release.gpu.b32 [%0], %1;" :: "l"(p), "r"(v) : "memory");
}
// packed fp32x2 FMA: d.lo += a.lo*b.lo ; d.hi += a.hi*b.hi
__device__ __forceinline__ void ffma2(unsigned long long& d,
                                      unsigned long long a,
                                      unsigned long long b) {
    asm("fma.rn.f32x2 %0, %1, %2, %0;" : "+l"(d) : "l"(a), "l"(b));
}

__global__ void __launch_bounds__(256, 1) reset_flags_kernel() {
    if (threadIdx.x < Bc*NSLAB) g_flags[threadIdx.x] = 0;
}

__global__ void __launch_bounds__(256, 1) seqconv_kernel(
    const float* __restrict__ X, const float* __restrict__ Wt,
    const float* __restrict__ bias, float* __restrict__ out)
{
    extern __shared__ char smem[];
    float*  sW      = (float*)(smem + OFF_W);
    float2* ring    = (float2*)(smem + OFF_RING);
    unsigned long long* ringU = (unsigned long long*)(smem + OFF_RING);
    float*  orig_sc = (float*)(smem + OFF_ORIG);
    float*  red     = (float*)(smem + OFF_RED);
    float*  sbias   = (float*)(smem + OFF_BIAS);

    const int t    = threadIdx.x;
    const int slab = blockIdx.x;
    const int b    = blockIdx.y;
    const int w0   = slab * WS;

    // ---- init: weights into smem, layout [tap][co] (co contiguous) ----
    for (int e = t; e < 576*64; e += 256) {
        int co = e & 63, tap = e >> 6;
        sW[e] = Wt[co*576 + tap];
    }
    if (t < 64) sbias[t] = bias[t];

    // ---- init: rows 0,1 (original) into ring slots 0,1 (dup, halo) + out ----
    for (int row = 0; row < 2; ++row) {
        for (int e = t; e < Cc*RW; e += 256) {
            int ci = e / RW, c = e - ci*RW;
            int gw = w0 - 1 + c;
            float v = ((unsigned)gw < (unsigned)Wc)
                        ? X[((b*Cc + ci)*Hc + row)*Wc + gw] : 0.f;
            ring[row*RSLOT + ci*RW + c] = make_float2(v, v);
            if ((unsigned)(c-1) < (unsigned)WS)
                out[((b*Cc + ci)*Hc + row)*Wc + w0 + (c-1)] = v;
        }
    }
    // ---- init: original row 2 into orig buffer 0 (slot 3, orig_sc buf 0) ----
    for (int e = t; e < Cc*RW; e += 256) {
        int ci = e / RW, c = e - ci*RW;
        int gw = w0 - 1 + c;
        float v = ((unsigned)gw < (unsigned)Wc)
                    ? X[((b*Cc + ci)*Hc + 2)*Wc + gw] : 0.f;
        ring[3*RSLOT + ci*RW + c] = make_float2(v, v);
        if ((unsigned)(c-1) < (unsigned)WS) orig_sc[ci*WS + (c-1)] = v;
    }
    __syncthreads();
    if (t == 0) { __threadfence(); st_rel(&g_flags[b*NSLAB + slab], 1); }

    // compute decomposition: thread = (ci group of 16) x (8 co) x (2 w)
    const int ci_g = t >> 6;            // 0..3
    const int rr   = t & 63;
    const int co0  = (rr >> 3) * 8;     // 0,8,...,56
    const int w_b  = (rr & 7) * 2;      // 0,2,...,14 (slab-local)
    const int ci0  = ci_g * 16;

    // epilogue decomposition: thread = 1 co x 4 w
    const int eco = t >> 2;             // 0..63
    const int ew4 = (t & 3) * 4;        // 0,4,8,12

    int* flagL = (slab > 0)        ? &g_flags[b*NSLAB + slab - 1] : (int*)0;
    int* flagR = (slab < NSLAB-1)  ? &g_flags[b*NSLAB + slab + 1] : (int*)0;

    for (int pos = 2; pos < Hc; ++pos) {
        const int slotA = (pos - 2) % 3;   // updated row pos-2
        const int slotB = (pos - 1) % 3;   // updated row pos-1
        const int slotN = pos % 3;         // updated row pos goes here
        const int bufC  = pos & 1;         // orig buffer for row pos
        const int bufN  = bufC ^ 1;        // orig buffer for row pos+1

        // --- prefetch ORIGINAL row pos+1 into registers (in flight during
        //     halo spin + compute; committed to smem after compute) ---
        float pf[NPF];
        {
            const bool have = (pos + 1) < Hc;
            const float* Xrow = X + ((size_t)(b*Cc))*Hc*Wc + (size_t)(pos+1)*Wc;
            #pragma unroll
            for (int i = 0; i < NPF; ++i) {
                int e = t + i*256;
                float v = 0.f;
                if (have && e < Cc*RW) {
                    int ci = e / RW, c = e - ci*RW;
                    int gw = w0 - 1 + c;
                    if ((unsigned)gw < (unsigned)Wc)
                        v = Xrow[(size_t)ci*Hc*Wc + gw];
                }
                pf[i] = v;
            }
        }

        // --- neighbor halo of updated row pos-1 (from gmem out, flag-gated) ---
        if (t < 64) {
            float v = 0.f;
            if (flagL) {
                while (ld_acq(flagL) < pos - 1) { }
                v = out[((b*Cc + t)*Hc + (pos-1))*Wc + (w0 - 1)];
            }
            ring[slotB*RSLOT + t*RW + 0] = make_float2(v, v);
        } else if (t < 128) {
            int ci = t - 64;
            float v = 0.f;
            if (flagR) {
                while (ld_acq(flagR) < pos - 1) { }
                v = out[((b*Cc + ci)*Hc + (pos-1))*Wc + (w0 + WS)];
            }
            ring[slotB*RSLOT + ci*RW + (RW-1)] = make_float2(v, v);
        }
        __syncthreads();

        // --- partial conv: 16 ci x 3 kh x 3 kw, 8 co x 2 w per thread ---
        unsigned long long acc[8];
        #pragma unroll
        for (int i = 0; i < 8; ++i) acc[i] = 0ull;

        const unsigned long long* rbase0 = ringU + slotA*RSLOT     + ci0*RW + w_b;
        const unsigned long long* rbase1 = ringU + slotB*RSLOT     + ci0*RW + w_b;
        const unsigned long long* rbase2 = ringU + (3+bufC)*RSLOT  + ci0*RW + w_b;
        const float* wbase = sW + (ci0*9)*64 + co0;

        #pragma unroll 4
        for (int cii = 0; cii < 16; ++cii) {
            #pragma unroll
            for (int kh = 0; kh < 3; ++kh) {
                const unsigned long long* rp =
                    (kh == 0 ? rbase0 : kh == 1 ? rbase1 : rbase2) + cii*RW;
                unsigned long long v0 = rp[0], v1 = rp[1], v2 = rp[2], v3 = rp[3];
                const float* wk = wbase + (cii*9 + kh*3)*64;
                #pragma unroll
                for (int kw = 0; kw < 3; ++kw) {
                    ulonglong2 wa  = *(const ulonglong2*)(wk);       // co0..co0+3
                    ulonglong2 wb2 = *(const ulonglong2*)(wk + 4);   // co0+4..co0+7
                    wk += 64;
                    unsigned long long dA = (kw == 0) ? v0 : (kw == 1) ? v1 : v2;
                    unsigned long long dB = (kw == 0) ? v1 : (kw == 1) ? v2 : v3;
                    ffma2(acc[0], wa.x,  dA);
                    ffma2(acc[1], wa.y,  dA);
                    ffma2(acc[2], wb2.x, dA);
                    ffma2(acc[3], wb2.y, dA);
                    ffma2(acc[4], wa.x,  dB);
                    ffma2(acc[5], wa.y,  dB);
                    ffma2(acc[6], wb2.x, dB);
                    ffma2(acc[7], wb2.y, dB);
                }
            }
        }

        // --- commit prefetched original row pos+1 to smem (buffer bufN) ---
        {
            #pragma unroll
            for (int i = 0; i < NPF; ++i) {
                int e = t + i*256;
                if (e < Cc*RW) {
                    int ci = e / RW, c = e - ci*RW;
                    ring[(3+bufN)*RSLOT + ci*RW + c] = make_float2(pf[i], pf[i]);
                    if ((unsigned)(c-1) < (unsigned)WS)
                        orig_sc[bufN*(64*16) + ci*WS + (c-1)] = pf[i];
                }
            }
        }

        // --- write partials: red[(ci_g*16 + w)*68 + co], co-pair packed ---
        {
            int base0 = (ci_g*16 + w_b) * 68 + co0;
            int base1 = base0 + 68;
            *(unsigned long long*)(red + base0 + 0) = acc[0];
            *(unsigned long long*)(red + base0 + 2) = acc[1];
            *(unsigned long long*)(red + base0 + 4) = acc[2];
            *(unsigned long long*)(red + base0 + 6) = acc[3];
            *(unsigned long long*)(red + base1 + 0) = acc[4];
            *(unsigned long long*)(red + base1 + 2) = acc[5];
            *(unsigned long long*)(red + base1 + 4) = acc[6];
            *(unsigned long long*)(red + base1 + 6) = acc[7];
        }
        __syncthreads();

        // --- epilogue: reduce 4 ci-groups, +bias, tanh, +orig, write out+ring ---
        {
            float s0 = 0.f, s1 = 0.f, s2 = 0.f, s3 = 0.f;
            #pragma unroll
            for (int g = 0; g < 4; ++g) {
                const float* rg = red + (g*16 + ew4)*68 + eco;
                s0 += rg[0];
                s1 += rg[68];
                s2 += rg[136];
                s3 += rg[204];
            }
            float bb = sbias[eco];
            float4 og = *(const float4*)(orig_sc + bufC*(64*16) + eco*WS + ew4);
            float r0 = og.x + tanhf(s0 + bb);
            float r1 = og.y + tanhf(s1 + bb);
            float r2 = og.z + tanhf(s2 + bb);
            float r3 = og.w + tanhf(s3 + bb);
            *(float4*)(out + ((b*Cc + eco)*Hc + pos)*Wc + w0 + ew4) =
                make_float4(r0, r1, r2, r3);
            float2* rn = ring + slotN*RSLOT + eco*RW + 1 + ew4;
            rn[0] = make_float2(r0, r0);
            rn[1] = make_float2(r1, r1);
            rn[2] = make_float2(r2, r2);
            rn[3] = make_float2(r3, r3);
        }
        __syncthreads();
        if (t == 0) { __threadfence(); st_rel(&g_flags[b*NSLAB + slab], pos); }
    }
}

extern "C" void kernel_launch(void* const* d_in, const int* in_sizes, int n_in,
                              void* d_out, int out_size) {
    const float* X    = (const float*)d_in[0];
    const float* Wt   = (const float*)d_in[1];
    const float* bias = (const float*)d_in[2];
    float* out = (float*)d_out;

    cudaFuncSetAttribute(seqconv_kernel,
                         cudaFuncAttributeMaxDynamicSharedMemorySize, SMEM_TOTAL);

    reset_flags_kernel<<<1, 256>>>();
    dim3 grid(NSLAB, Bc);
    seqconv_kernel<<<grid, 256, SMEM_TOTAL>>>(X, Wt, bias, out);
}